// round 14
// baseline (speedup 1.0000x reference)
#include <cuda_runtime.h>
#include <math.h>
#include <stdint.h>

// ---------------------------------------------------------------- dims
#define Bb 128
#define Ss 512
#define Hh 1024
#define MIDm 512
#define FEATf 576
#define BH 131072      // B*H
#define BMID 65536     // B*MID
#define B4H 524288     // B*4H
#define NX 37748736    // S*FEAT*B   (X stored [t][k][b])

// ---------------------------------------------------------------- scratch
constexpr size_t OFF_X    = 0;
constexpr size_t OFF_WSI  = OFF_X + NX;                    // [576][512]
constexpr size_t OFF_WSH  = OFF_WSI + 576*512;             // [1024][512]
constexpr size_t OFF_WMX1 = OFF_WSH + 1024*512;            // [576][1024]
constexpr size_t OFF_WMH1 = OFF_WMX1 + 576*1024;           // [1024][1024]
constexpr size_t OFF_WIH1 = OFF_WMH1 + 1024*1024;          // [576][4096]
constexpr size_t OFF_WHH1 = OFF_WIH1 + (size_t)576*4096;   // [1024][4096]
constexpr size_t OFF_WMX2 = OFF_WHH1 + (size_t)1024*4096;  // [1024][1024]
constexpr size_t OFF_WMH2 = OFF_WMX2 + 1024*1024;
constexpr size_t OFF_WIH2 = OFF_WMH2 + 1024*1024;          // [1024][4096]
constexpr size_t OFF_WHH2 = OFF_WIH2 + (size_t)1024*4096;  // [1024][4096]
// precomputed x-dependent GEMM outputs, all timesteps
constexpr size_t OFF_ZBA_ALL = OFF_WHH2 + (size_t)1024*4096;   // [S][B][512]
constexpr size_t OFF_M1A_ALL = OFF_ZBA_ALL + (size_t)Ss*BMID;  // [S][B][1024]
constexpr size_t OFF_Z1A_ALL = OFF_M1A_ALL + (size_t)Ss*BH;    // [S][B][4096]
// states (k-major [h][b]) + per-step buffers
constexpr size_t OFF_H1T  = OFF_Z1A_ALL + (size_t)Ss*B4H;
constexpr size_t OFF_C1T  = OFF_H1T + BH;
constexpr size_t OFF_H2T  = OFF_C1T + BH;
constexpr size_t OFF_C2T  = OFF_H2T + BH;
constexpr size_t OFF_X2T  = OFF_C2T + BH;
constexpr size_t OFF_MM1  = OFF_X2T + BH;
constexpr size_t OFF_MM2  = OFF_MM1 + BH;
constexpr size_t OFF_ZBB  = OFF_MM2 + BH;          // 8 x [128][512]
constexpr size_t OFF_M1B  = OFF_ZBB + 8*BMID;      // 8 x [128][1024]
constexpr size_t OFF_Z1B  = OFF_M1B + 8*BH;        // 4 x [128][4096]
constexpr size_t OFF_M2A  = OFF_Z1B + 4*B4H;       // 4 x [128][1024]
constexpr size_t OFF_M2B  = OFF_M2A + 4*BH;        // 4 x [128][1024]
constexpr size_t OFF_Z2A  = OFF_M2B + 4*BH;        // 4 x [128][4096]
constexpr size_t OFF_Z2B  = OFF_Z2A + 4*B4H;       // 4 x [128][4096]
constexpr size_t OFF_SBUF = OFF_Z2B + 4*B4H;
constexpr size_t SCRATCH_TOTAL = OFF_SBUF + 128;

__device__ __align__(16) float g_scratch[SCRATCH_TOTAL];
__device__ unsigned g_leaf[16 * 64];   // 256B-strided leaf counters
__device__ unsigned g_master = 0;
__device__ unsigned g_bar_gen = 0;
__device__ float    g_flag = 0.0f;

// ---------------------------------------------------------------- output layout
#define OUT_H2F   67108864            // B*S*H
#define OUT_C2F   (OUT_H2F + BH)
#define OUT_FLAGS (OUT_C2F + BH)

__device__ __forceinline__ float sigm(float x) { return 1.0f / (1.0f + expf(-x)); }

// ---------------------------------------------------------------- tree grid barrier
__device__ __forceinline__ void grid_barrier(unsigned nct, int bid)
{
    __syncthreads();
    if (threadIdx.x == 0) {
        unsigned gen = *(volatile unsigned*)&g_bar_gen;
        __threadfence();                      // release this CTA's writes
        const int leaf = bid & 15;
        const unsigned cnt = (nct - (unsigned)leaf + 15u) >> 4;
        bool released = false;
        unsigned prev = atomicAdd(&g_leaf[leaf * 64], 1u);
        if (prev == cnt - 1u) {
            g_leaf[leaf * 64] = 0u;
            __threadfence();
            unsigned pm = atomicAdd(&g_master, 1u);
            if (pm == 15u) {
                g_master = 0u;
                __threadfence();
                *(volatile unsigned*)&g_bar_gen = gen + 1u;
                released = true;
            }
        }
        if (!released)
            while (*(volatile unsigned*)&g_bar_gen == gen) { __nanosleep(32); }
        __threadfence();                      // acquire
    }
    __syncthreads();
}

// ---------------------------------------------------------------- GEMM tile
// out[0:128, n0:n0+64] = At[k0:k0+32*nch, 0:128]^T @ Wt[k0:.., n0:n0+64]
// At k-major [K][128]; Wt k-major [K][N]; out row-major [128][N] (ldo == ldw).
// 256 threads; 8(m)x4(n) microtile via packed f32x2; cp.async double buffer.
__device__ __forceinline__ void cp16(uint32_t dst, const float* src) {
    asm volatile("cp.async.cg.shared.global [%0], [%1], 16;" :: "r"(dst), "l"(src));
}

template<bool STREAM>
__device__ void gemm_tile(float* smemf, uint32_t smemu,
                          const float* __restrict__ At,
                          const float* __restrict__ Wt, int ldw,
                          int k0, int nch, int n0,
                          float* __restrict__ outp)
{
    const int tid = threadIdx.x;
    const int tm = tid >> 4, tn = tid & 15;

    unsigned long long acc[16];
#pragma unroll
    for (int i = 0; i < 16; i++) acc[i] = 0ull;

    auto copy_chunk = [&](int c) {
        const int buf = c & 1;
        const float* As = At + (size_t)(k0 + c * 32) * 128;
        uint32_t adst = smemu + buf * 16384;
#pragma unroll
        for (int p = 0; p < 4; p++)
            cp16(adst + (p * 256 + tid) * 16, As + (p * 256 + tid) * 4);
        const float* Ws = Wt + (size_t)(k0 + c * 32) * ldw + n0;
        uint32_t wdst = smemu + 32768 + buf * 8192;
#pragma unroll
        for (int p = 0; p < 2; p++) {
            int r = (tid >> 4) + p * 16;
            cp16(wdst + (r * 64 + (tid & 15) * 4) * 4, Ws + (size_t)r * ldw + (tid & 15) * 4);
        }
        asm volatile("cp.async.commit_group;");
    };

    copy_chunk(0);
    for (int c = 0; c < nch; c++) {
        if (c + 1 < nch) { copy_chunk(c + 1); asm volatile("cp.async.wait_group 1;"); }
        else             { asm volatile("cp.async.wait_group 0;"); }
        __syncthreads();
        const float* cA = smemf + (c & 1) * 4096;
        const float* cW = smemf + 8192 + (c & 1) * 2048;
#pragma unroll 8
        for (int k = 0; k < 32; k++) {
            ulonglong2 Alo = *(const ulonglong2*)(cA + k * 128 + tm * 8);
            ulonglong2 Ahi = *(const ulonglong2*)(cA + k * 128 + tm * 8 + 4);
            float4 w = *(const float4*)(cW + k * 64 + tn * 4);
            unsigned long long w0, w1, w2, w3;
            asm("mov.b64 %0,{%1,%1};" : "=l"(w0) : "r"(__float_as_uint(w.x)));
            asm("mov.b64 %0,{%1,%1};" : "=l"(w1) : "r"(__float_as_uint(w.y)));
            asm("mov.b64 %0,{%1,%1};" : "=l"(w2) : "r"(__float_as_uint(w.z)));
            asm("mov.b64 %0,{%1,%1};" : "=l"(w3) : "r"(__float_as_uint(w.w)));
#define FX2(i, a, b) asm("fma.rn.f32x2 %0, %1, %2, %0;" : "+l"(acc[i]) : "l"(a), "l"(b))
            FX2(0,  Alo.x, w0); FX2(1,  Alo.x, w1); FX2(2,  Alo.x, w2); FX2(3,  Alo.x, w3);
            FX2(4,  Alo.y, w0); FX2(5,  Alo.y, w1); FX2(6,  Alo.y, w2); FX2(7,  Alo.y, w3);
            FX2(8,  Ahi.x, w0); FX2(9,  Ahi.x, w1); FX2(10, Ahi.x, w2); FX2(11, Ahi.x, w3);
            FX2(12, Ahi.y, w0); FX2(13, Ahi.y, w1); FX2(14, Ahi.y, w2); FX2(15, Ahi.y, w3);
#undef FX2
        }
        __syncthreads();
    }

#pragma unroll
    for (int r = 0; r < 4; r++) {
        uint32_t l0,h0,l1,h1,l2,h2,l3,h3;
        asm("mov.b64 {%0,%1},%2;" : "=r"(l0), "=r"(h0) : "l"(acc[r*4+0]));
        asm("mov.b64 {%0,%1},%2;" : "=r"(l1), "=r"(h1) : "l"(acc[r*4+1]));
        asm("mov.b64 {%0,%1},%2;" : "=r"(l2), "=r"(h2) : "l"(acc[r*4+2]));
        asm("mov.b64 {%0,%1},%2;" : "=r"(l3), "=r"(h3) : "l"(acc[r*4+3]));
        float4 v0 = make_float4(__uint_as_float(l0), __uint_as_float(l1), __uint_as_float(l2), __uint_as_float(l3));
        float4 v1 = make_float4(__uint_as_float(h0), __uint_as_float(h1), __uint_as_float(h2), __uint_as_float(h3));
        float4* p0 = (float4*)&outp[(size_t)(tm*8 + r*2    ) * ldw + n0 + tn*4];
        float4* p1 = (float4*)&outp[(size_t)(tm*8 + r*2 + 1) * ldw + n0 + tn*4];
        if (STREAM) { __stcs(p0, v0); __stcs(p1, v1); }
        else        { *p0 = v0; *p1 = v1; }
    }
}

// ---------------------------------------------------------------- persistent kernel
__global__ void __launch_bounds__(256, 2)
enc_persistent(const float* __restrict__ b_bd, const float* __restrict__ vs,
               const float* __restrict__ b1,   const float* __restrict__ b2,
               float* __restrict__ out, int out_size)
{
    extern __shared__ float smemf[];
    const uint32_t smemu = (uint32_t)__cvta_generic_to_shared(smemf);

    const unsigned nct = gridDim.x;
    const int bid = blockIdx.x, tid = threadIdx.x;
    float* base = g_scratch;

    float* h1t = base + OFF_H1T;  float* c1t = base + OFF_C1T;
    float* h2t = base + OFF_H2T;  float* c2t = base + OFF_C2T;
    float* x2t = base + OFF_X2T;
    float* mm1 = base + OFF_MM1;  float* mm2 = base + OFF_MM2;
    float* sbuf = base + OFF_SBUF;

    // ================= pre-pass: all x-dependent GEMMs, all t ====
    // zba_all/m1a_all/z1a_all; 88 tiles per t, K=576 (18 chunks), streamed out.
    for (int id = bid; id < 512 * 88; id += nct) {
        int t = id / 88, r = id - t * 88;
        const float* At = base + OFF_X + (size_t)t * FEATf * Bb;
        if (r < 8)
            gemm_tile<true>(smemf, smemu, At, base + OFF_WSI, 512, 0, 18, r * 64,
                            base + OFF_ZBA_ALL + (size_t)t * BMID);
        else if (r < 24)
            gemm_tile<true>(smemf, smemu, At, base + OFF_WMX1, 1024, 0, 18, (r - 8) * 64,
                            base + OFF_M1A_ALL + (size_t)t * BH);
        else
            gemm_tile<true>(smemf, smemu, At, base + OFF_WIH1, 4096, 0, 18, (r - 24) * 64,
                            base + OFF_Z1A_ALL + (size_t)t * B4H);
    }
    // zero recurrent state (h1t,c1t,h2t,c2t contiguous)
    for (int i = bid * 256 + tid; i < 4 * BH; i += nct * 256) h1t[i] = 0.0f;
    grid_barrier(nct, bid);

    for (int t = 0; t < Ss; t++) {
        // ---- Phase A : h-dependent GEMMs, 192 tiles (K=128, 4 chunks) ----
        for (int id = bid; id < 192; id += nct) {
            if (id < 64) {
                int q = id >> 3, j = id & 7;
                gemm_tile<false>(smemf, smemu, h1t, base + OFF_WSH, 512, q * 128, 4, j * 64,
                                 base + OFF_ZBB + (size_t)q * BMID);
            } else {
                int i2 = id - 64, q = i2 >> 4, j = i2 & 15;
                gemm_tile<false>(smemf, smemu, h1t, base + OFF_WMH1, 1024, q * 128, 4, j * 64,
                                 base + OFF_M1B + (size_t)q * BH);
            }
        }
        grid_barrier(nct, bid);

        // ---- Phase A2 : mm1 combine + boundary ----
        {
            const float* m1aA = base + OFF_M1A_ALL + (size_t)t * BH;
            if (bid >= 16) {
                const float* b0 = base + OFF_M1B;
                for (int idx = (bid - 16) * 256 + tid; idx < BH; idx += (nct - 16) * 256) {
                    int b = idx >> 10, h = idx & 1023;
                    size_t s = (size_t)b * 1024 + h;
                    float mb = b0[s] + b0[BH + s] + b0[2*BH + s] + b0[3*BH + s]
                             + b0[4*BH + s] + b0[5*BH + s] + b0[6*BH + s] + b0[7*BH + s];
                    mm1[h * 128 + b] = __ldcs(&m1aA[s]) * mb;
                }
            } else {
                const float* zbaA = base + OFF_ZBA_ALL + (size_t)t * BMID;
                const float* q0 = base + OFF_ZBB;
                int w = tid >> 5, lane = tid & 31;
                int b = bid * 8 + w;
                float sum = 0.0f;
                for (int j = lane; j < MIDm; j += 32) {
                    size_t s = (size_t)b * 512 + j;
                    float z = __ldcs(&zbaA[s]) + b_bd[j]
                            + q0[s] + q0[BMID + s] + q0[2*BMID + s] + q0[3*BMID + s]
                            + q0[4*BMID + s] + q0[5*BMID + s] + q0[6*BMID + s] + q0[7*BMID + s];
                    sum += z * vs[j];
                }
#pragma unroll
                for (int o = 16; o > 0; o >>= 1) sum += __shfl_down_sync(0xffffffffu, sum, o);
                if (lane == 0) {
                    float p = 1.0f / (1.0f + expf(-sum));
                    float bin = (p > 0.5f) ? 1.0f : 0.0f;
                    float sv = p + (bin - p);
                    sbuf[b] = sv;
                    if (b == 0) {
                        g_flag = sv;
                        if (OUT_FLAGS + t < out_size) out[OUT_FLAGS + t] = sv;
                    }
                }
            }
        }
        grid_barrier(nct, bid);

        // ---- Phase B : z1b = mm1 @ Whh1^T, 256 tiles (K=256) ----
        for (int id = bid; id < 256; id += nct) {
            int q = id >> 6, j = id & 63;
            gemm_tile<false>(smemf, smemu, mm1, base + OFF_WHH1, 4096, q * 256, 8, j * 64,
                             base + OFF_Z1B + (size_t)q * B4H);
        }
        grid_barrier(nct, bid);

        // ---- Phase C : gates1 ----
        {
            const float* z1aA = base + OFF_Z1A_ALL + (size_t)t * B4H;
            const float* zb = base + OFF_Z1B;
            for (int idx = bid * 256 + tid; idx < BH; idx += nct * 256) {
                int b = idx >> 10, h = idx & 1023;
                size_t zi = (size_t)b * 4096 + h;
#define GSUM(g) (__ldcs(&z1aA[zi+(g)*1024]) + zb[zi+(g)*1024] + zb[B4H+zi+(g)*1024] \
                 + zb[2*B4H+zi+(g)*1024] + zb[3*B4H+zi+(g)*1024] + b1[(g)*1024+h])
                float iz = GSUM(0), fz = GSUM(1), gz = GSUM(2), oz = GSUM(3);
#undef GSUM
                int s = h * 128 + b;
                float cn = sigm(fz) * c1t[s] + sigm(iz) * tanhf(gz);
                float hn = sigm(oz) * tanhf(cn);
                float sv = sbuf[b];
                float om = 1.0f - sv;
                x2t[s] = hn * sv;
                h1t[s] = hn * om;
                c1t[s] = cn * om;
            }
        }
        grid_barrier(nct, bid);

        const float fl = *(volatile float*)&g_flag;

        if (fl > 0.5f) {
            // ---- Phase D : 384 tiles (K=256) ----
            for (int id = bid; id < 384; id += nct) {
                if (id < 64) {
                    int q = id >> 4, j = id & 15;
                    gemm_tile<false>(smemf, smemu, x2t, base + OFF_WMX2, 1024, q * 256, 8, j * 64,
                                     base + OFF_M2A + (size_t)q * BH);
                } else if (id < 128) {
                    int i2 = id - 64, q = i2 >> 4, j = i2 & 15;
                    gemm_tile<false>(smemf, smemu, h2t, base + OFF_WMH2, 1024, q * 256, 8, j * 64,
                                     base + OFF_M2B + (size_t)q * BH);
                } else {
                    int i2 = id - 128, q = i2 >> 6, j = i2 & 63;
                    gemm_tile<false>(smemf, smemu, x2t, base + OFF_WIH2, 4096, q * 256, 8, j * 64,
                                     base + OFF_Z2A + (size_t)q * B4H);
                }
            }
            grid_barrier(nct, bid);

            // ---- Phase D2 : combine mm2 ----
            {
                const float* a0 = base + OFF_M2A;
                const float* e0 = base + OFF_M2B;
                for (int idx = bid * 256 + tid; idx < BH; idx += nct * 256) {
                    int b = idx >> 10, h = idx & 1023;
                    size_t s = (size_t)b * 1024 + h;
                    float ma = a0[s] + a0[BH + s] + a0[2*BH + s] + a0[3*BH + s];
                    float mb = e0[s] + e0[BH + s] + e0[2*BH + s] + e0[3*BH + s];
                    mm2[h * 128 + b] = ma * mb;
                }
            }
            grid_barrier(nct, bid);

            // ---- Phase E : z2b, 256 tiles (K=256) ----
            for (int id = bid; id < 256; id += nct) {
                int q = id >> 6, j = id & 63;
                gemm_tile<false>(smemf, smemu, mm2, base + OFF_WHH2, 4096, q * 256, 8, j * 64,
                                 base + OFF_Z2B + (size_t)q * B4H);
            }
            grid_barrier(nct, bid);
        }

        // ---- Phase F : gates2 / copy (no trailing barrier; safe vs t+1) ----
        {
            const float* za = base + OFF_Z2A;
            const float* ze = base + OFF_Z2B;
            for (int idx = bid * 256 + tid; idx < BH; idx += nct * 256) {
                int b = idx >> 10, h = idx & 1023;
                size_t oidx = (size_t)b * Ss * Hh + (size_t)t * Hh + h;
                int s = h * 128 + b;
                if (fl > 0.5f) {
                    size_t zi = (size_t)b * 4096 + h;
#define GSUM(g) (za[zi+(g)*1024] + za[B4H+zi+(g)*1024] + za[2*B4H+zi+(g)*1024] + za[3*B4H+zi+(g)*1024] + \
                 ze[zi+(g)*1024] + ze[B4H+zi+(g)*1024] + ze[2*B4H+zi+(g)*1024] + ze[3*B4H+zi+(g)*1024] + b2[(g)*1024+h])
                    float iz = GSUM(0), fz = GSUM(1), gz = GSUM(2), oz = GSUM(3);
#undef GSUM
                    float cn = sigm(fz) * c2t[s] + sigm(iz) * tanhf(gz);
                    float hn = sigm(oz) * tanhf(cn);
                    h2t[s] = hn;
                    c2t[s] = cn;
                    out[oidx] = hn;
                } else {
                    out[oidx] = h2t[s];
                }
            }
        }
        // no barrier: everything F touches is >=1 full barrier away from any t+1 writer
    }

    // ---- tail: final states ----
    grid_barrier(nct, bid);
    for (int idx = bid * 256 + tid; idx < BH; idx += nct * 256) {
        int b = idx >> 10, h = idx & 1023;
        int s = h * 128 + b;
        if (OUT_H2F + idx < out_size) out[OUT_H2F + (size_t)b * 1024 + h] = h2t[s];
        if (OUT_C2F + idx < out_size) out[OUT_C2F + (size_t)b * 1024 + h] = c2t[s];
    }
}

// ---------------------------------------------------------------- weight transpose
// src [N][K] row-major  ->  dst [K][N]
__global__ void transpose_kernel(const float* __restrict__ src, float* __restrict__ dst,
                                 int N, int K)
{
    __shared__ float tile[32][33];
    int kb = blockIdx.x * 32, nb = blockIdx.y * 32;
    int tx = threadIdx.x, ty = threadIdx.y;
#pragma unroll
    for (int r = 0; r < 4; r++)
        tile[ty + r * 8][tx] = src[(size_t)(nb + ty + r * 8) * K + kb + tx];
    __syncthreads();
#pragma unroll
    for (int r = 0; r < 4; r++)
        dst[(size_t)(kb + ty + r * 8) * N + nb + tx] = tile[tx][ty + r * 8];
}

// ---------------------------------------------------------------- embedding gather
// X[t][f][b] (k-major per timestep); grid (Bb, Ss) so adjacent blocks share b-lines
__global__ void gather_kernel(const int* __restrict__ enc, const int* __restrict__ xenc,
                              const float* __restrict__ wemb, const float* __restrict__ xemb,
                              float* __restrict__ X)
{
    int b = blockIdx.x, t = blockIdx.y, tid = threadIdx.x;
    __shared__ int sid, sxid;
    if (tid == 0) { sid = enc[b * Ss + t]; sxid = xenc[b * Ss + t]; }
    __syncthreads();
    int id = sid, xid = sxid;
    float* dst = X + (size_t)t * FEATf * Bb + b;
    for (int f = tid; f < 512; f += 128)
        dst[(size_t)f * 128] = wemb[(size_t)id * 512 + f];
    int f = 512 + tid;
    if (f < 576)
        dst[(size_t)f * 128] = xemb[xid * 64 + (f - 512)];
}

// ----------------------------------------------------------------
extern "C" void kernel_launch(void* const* d_in, const int* in_sizes, int n_in,
                              void* d_out, int out_size)
{
    const int*   enc  = (const int*)d_in[0];
    const int*   xenc = (const int*)d_in[1];
    const float* wemb = (const float*)d_in[2];
    const float* xemb = (const float*)d_in[3];
    const float* Wsi  = (const float*)d_in[4];
    const float* Wsh  = (const float*)d_in[5];
    const float* b_bd = (const float*)d_in[6];
    const float* vs   = (const float*)d_in[7];
    const float* Wmx1 = (const float*)d_in[8];
    const float* Wmh1 = (const float*)d_in[9];
    const float* Wih1 = (const float*)d_in[10];
    const float* Whh1 = (const float*)d_in[11];
    const float* b1   = (const float*)d_in[12];
    const float* Wmx2 = (const float*)d_in[13];
    const float* Wmh2 = (const float*)d_in[14];
    const float* Wih2 = (const float*)d_in[15];
    const float* Whh2 = (const float*)d_in[16];
    const float* b2   = (const float*)d_in[17];
    float* out = (float*)d_out;

    float* base = nullptr;
    cudaGetSymbolAddress((void**)&base, g_scratch);

    gather_kernel<<<dim3(Bb, Ss), 128>>>(enc, xenc, wemb, xemb, base + OFF_X);

    struct TJ { const float* src; size_t dst; int N, K; };
    TJ jobs[10] = {
        { Wsi,  OFF_WSI,  512,  576  },
        { Wsh,  OFF_WSH,  512,  1024 },
        { Wmx1, OFF_WMX1, 1024, 576  },
        { Wmh1, OFF_WMH1, 1024, 1024 },
        { Wih1, OFF_WIH1, 4096, 576  },
        { Whh1, OFF_WHH1, 4096, 1024 },
        { Wmx2, OFF_WMX2, 1024, 1024 },
        { Wmh2, OFF_WMH2, 1024, 1024 },
        { Wih2, OFF_WIH2, 4096, 1024 },
        { Whh2, OFF_WHH2, 4096, 1024 },
    };
    for (int i = 0; i < 10; i++)
        transpose_kernel<<<dim3(jobs[i].K / 32, jobs[i].N / 32), dim3(32, 8)>>>(
            jobs[i].src, base + jobs[i].dst, jobs[i].N, jobs[i].K);

    int nsm = 148;
    cudaDeviceGetAttribute(&nsm, cudaDevAttrMultiProcessorCount, 0);

    const int smem_bytes = (2 * 4096 + 2 * 2048) * 4;  // 49152
    cudaFuncSetAttribute(enc_persistent, cudaFuncAttributeMaxDynamicSharedMemorySize, smem_bytes);

    int occ = 1;
    cudaOccupancyMaxActiveBlocksPerMultiprocessor(&occ, enc_persistent, 256, smem_bytes);
    if (occ < 1) occ = 1;
    if (occ > 2) occ = 2;

    enc_persistent<<<nsm * occ, 256, smem_bytes>>>(b_bd, vs, b1, b2, out, out_size);
}

// round 16
// speedup vs baseline: 1.4348x; 1.4348x over previous
#include <cuda_runtime.h>
#include <math.h>
#include <stdint.h>

// ---------------------------------------------------------------- dims
#define Bb 128
#define Ss 512
#define Hh 1024
#define MIDm 512
#define FEATf 576
#define BH 131072      // B*H
#define BMID 65536     // B*MID
#define B4H 524288     // B*4H
#define NX 37748736    // S*FEAT*B   (X stored [t][k][b])

// ---------------------------------------------------------------- scratch
constexpr size_t OFF_X    = 0;
constexpr size_t OFF_WSI  = OFF_X + NX;                    // [576][512]
constexpr size_t OFF_WSH  = OFF_WSI + 576*512;             // [1024][512]
constexpr size_t OFF_WMX1 = OFF_WSH + 1024*512;            // [576][1024]
constexpr size_t OFF_WMH1 = OFF_WMX1 + 576*1024;           // [1024][1024]
constexpr size_t OFF_WIH1 = OFF_WMH1 + 1024*1024;          // [576][4096]
constexpr size_t OFF_WHH1 = OFF_WIH1 + (size_t)576*4096;   // [1024][4096]
constexpr size_t OFF_WMX2 = OFF_WHH1 + (size_t)1024*4096;  // [1024][1024]
constexpr size_t OFF_WMH2 = OFF_WMX2 + 1024*1024;
constexpr size_t OFF_WIH2 = OFF_WMH2 + 1024*1024;          // [1024][4096]
constexpr size_t OFF_WHH2 = OFF_WIH2 + (size_t)1024*4096;  // [1024][4096]
constexpr size_t OFF_H1T  = OFF_WHH2 + (size_t)1024*4096;  // [1024][128] k-major
constexpr size_t OFF_C1T  = OFF_H1T + BH;
constexpr size_t OFF_H2T  = OFF_C1T + BH;
constexpr size_t OFF_C2T  = OFF_H2T + BH;
constexpr size_t OFF_X2T  = OFF_C2T + BH;
constexpr size_t OFF_MM1  = OFF_X2T + BH;
constexpr size_t OFF_MM2  = OFF_MM1 + BH;
constexpr size_t OFF_ZBA  = OFF_MM2 + BH;          // 2 x [128][512]
constexpr size_t OFF_ZBB  = OFF_ZBA + 2*BMID;      // 4 x [128][512]
constexpr size_t OFF_M1A  = OFF_ZBB + 4*BMID;      // 2 x [128][1024]
constexpr size_t OFF_M1B  = OFF_M1A + 2*BH;        // 4 x [128][1024]
constexpr size_t OFF_Z1A  = OFF_M1B + 4*BH;        // 2 x [128][4096]
constexpr size_t OFF_Z1B  = OFF_Z1A + 2*B4H;       // 4 x [128][4096]
constexpr size_t OFF_M2A  = OFF_Z1B + 4*B4H;       // 4 x [128][1024]
constexpr size_t OFF_M2B  = OFF_M2A + 4*BH;
constexpr size_t OFF_Z2A  = OFF_M2B + 4*BH;        // 4 x [128][4096]
constexpr size_t OFF_Z2B  = OFF_Z2A + 4*B4H;
constexpr size_t OFF_SBUF = OFF_Z2B + 4*B4H;
constexpr size_t SCRATCH_TOTAL = OFF_SBUF + 128;

__device__ __align__(16) float g_scratch[SCRATCH_TOTAL];
__device__ unsigned g_leaf[16 * 64];   // 256B-strided leaf counters
__device__ unsigned g_master = 0;
__device__ unsigned g_bar_gen = 0;
__device__ unsigned g_work = 0;
__device__ float    g_flag = 0.0f;

// ---------------------------------------------------------------- output layout
#define OUT_H2F   67108864            // B*S*H
#define OUT_C2F   (OUT_H2F + BH)
#define OUT_FLAGS (OUT_C2F + BH)

__device__ __forceinline__ float sigm(float x) { return 1.0f / (1.0f + expf(-x)); }

// ---------------------------------------------------------------- tree grid barrier
// On exit: g_work == 0, all pre-barrier global writes visible.
__device__ __forceinline__ void grid_barrier(unsigned nct, int bid)
{
    __syncthreads();
    if (threadIdx.x == 0) {
        unsigned gen = *(volatile unsigned*)&g_bar_gen;
        __threadfence();                      // release this CTA's writes
        const int leaf = bid & 15;
        const unsigned cnt = (nct - (unsigned)leaf + 15u) >> 4;
        bool released = false;
        unsigned prev = atomicAdd(&g_leaf[leaf * 64], 1u);
        if (prev == cnt - 1u) {
            g_leaf[leaf * 64] = 0u;
            __threadfence();
            unsigned pm = atomicAdd(&g_master, 1u);
            if (pm == 15u) {
                g_master = 0u;
                *(volatile unsigned*)&g_work = 0u;
                __threadfence();
                *(volatile unsigned*)&g_bar_gen = gen + 1u;
                released = true;
            }
        }
        if (!released)
            while (*(volatile unsigned*)&g_bar_gen == gen) { __nanosleep(32); }
        __threadfence();                      // acquire
    }
    __syncthreads();
}

// ---------------------------------------------------------------- GEMM tile
// out[0:128, n0:n0+64] = At[k0:k0+32*nch, 0:128]^T @ Wt[k0:.., n0:n0+64]
// At k-major [K][128]; Wt k-major [K][N]; out row-major [128][N] (ldo == ldw).
// 256 threads; 8(m)x4(n) microtile via packed f32x2; cp.async double buffer.
__device__ __forceinline__ void cp16(uint32_t dst, const float* src) {
    asm volatile("cp.async.cg.shared.global [%0], [%1], 16;" :: "r"(dst), "l"(src));
}

__device__ void gemm_tile(float* smemf, uint32_t smemu,
                          const float* __restrict__ At,
                          const float* __restrict__ Wt, int ldw,
                          int k0, int nch, int n0,
                          float* __restrict__ outp)
{
    const int tid = threadIdx.x;
    const int tm = tid >> 4, tn = tid & 15;

    unsigned long long acc[16];
#pragma unroll
    for (int i = 0; i < 16; i++) acc[i] = 0ull;

    auto copy_chunk = [&](int c) {
        const int buf = c & 1;
        const float* As = At + (size_t)(k0 + c * 32) * 128;
        uint32_t adst = smemu + buf * 16384;
#pragma unroll
        for (int p = 0; p < 4; p++)
            cp16(adst + (p * 256 + tid) * 16, As + (p * 256 + tid) * 4);
        const float* Ws = Wt + (size_t)(k0 + c * 32) * ldw + n0;
        uint32_t wdst = smemu + 32768 + buf * 8192;
#pragma unroll
        for (int p = 0; p < 2; p++) {
            int r = (tid >> 4) + p * 16;
            cp16(wdst + (r * 64 + (tid & 15) * 4) * 4, Ws + (size_t)r * ldw + (tid & 15) * 4);
        }
        asm volatile("cp.async.commit_group;");
    };

    copy_chunk(0);
    for (int c = 0; c < nch; c++) {
        if (c + 1 < nch) { copy_chunk(c + 1); asm volatile("cp.async.wait_group 1;"); }
        else             { asm volatile("cp.async.wait_group 0;"); }
        __syncthreads();
        const float* cA = smemf + (c & 1) * 4096;
        const float* cW = smemf + 8192 + (c & 1) * 2048;
#pragma unroll 8
        for (int k = 0; k < 32; k++) {
            ulonglong2 Alo = *(const ulonglong2*)(cA + k * 128 + tm * 8);
            ulonglong2 Ahi = *(const ulonglong2*)(cA + k * 128 + tm * 8 + 4);
            float4 w = *(const float4*)(cW + k * 64 + tn * 4);
            unsigned long long w0, w1, w2, w3;
            asm("mov.b64 %0,{%1,%1};" : "=l"(w0) : "r"(__float_as_uint(w.x)));
            asm("mov.b64 %0,{%1,%1};" : "=l"(w1) : "r"(__float_as_uint(w.y)));
            asm("mov.b64 %0,{%1,%1};" : "=l"(w2) : "r"(__float_as_uint(w.z)));
            asm("mov.b64 %0,{%1,%1};" : "=l"(w3) : "r"(__float_as_uint(w.w)));
#define FX2(i, a, b) asm("fma.rn.f32x2 %0, %1, %2, %0;" : "+l"(acc[i]) : "l"(a), "l"(b))
            FX2(0,  Alo.x, w0); FX2(1,  Alo.x, w1); FX2(2,  Alo.x, w2); FX2(3,  Alo.x, w3);
            FX2(4,  Alo.y, w0); FX2(5,  Alo.y, w1); FX2(6,  Alo.y, w2); FX2(7,  Alo.y, w3);
            FX2(8,  Ahi.x, w0); FX2(9,  Ahi.x, w1); FX2(10, Ahi.x, w2); FX2(11, Ahi.x, w3);
            FX2(12, Ahi.y, w0); FX2(13, Ahi.y, w1); FX2(14, Ahi.y, w2); FX2(15, Ahi.y, w3);
#undef FX2
        }
        __syncthreads();
    }

#pragma unroll
    for (int r = 0; r < 4; r++) {
        uint32_t l0,h0,l1,h1,l2,h2,l3,h3;
        asm("mov.b64 {%0,%1},%2;" : "=r"(l0), "=r"(h0) : "l"(acc[r*4+0]));
        asm("mov.b64 {%0,%1},%2;" : "=r"(l1), "=r"(h1) : "l"(acc[r*4+1]));
        asm("mov.b64 {%0,%1},%2;" : "=r"(l2), "=r"(h2) : "l"(acc[r*4+2]));
        asm("mov.b64 {%0,%1},%2;" : "=r"(l3), "=r"(h3) : "l"(acc[r*4+3]));
        *(float4*)&outp[(size_t)(tm*8 + r*2    ) * ldw + n0 + tn*4] =
            make_float4(__uint_as_float(l0), __uint_as_float(l1), __uint_as_float(l2), __uint_as_float(l3));
        *(float4*)&outp[(size_t)(tm*8 + r*2 + 1) * ldw + n0 + tn*4] =
            make_float4(__uint_as_float(h0), __uint_as_float(h1), __uint_as_float(h2), __uint_as_float(h3));
    }
}

// ---------------------------------------------------------------- persistent kernel
__global__ void __launch_bounds__(256, 2)
enc_persistent(const float* __restrict__ b_bd, const float* __restrict__ vs,
               const float* __restrict__ b1,   const float* __restrict__ b2,
               float* __restrict__ out, int out_size)
{
    extern __shared__ float smemf[];
    const uint32_t smemu = (uint32_t)__cvta_generic_to_shared(smemf);
    __shared__ int s_id;

    const unsigned nct = gridDim.x;
    const int bid = blockIdx.x, tid = threadIdx.x;
    float* base = g_scratch;

    float* h1t = base + OFF_H1T;  float* c1t = base + OFF_C1T;
    float* h2t = base + OFF_H2T;  float* c2t = base + OFF_C2T;
    float* x2t = base + OFF_X2T;
    float* mm1 = base + OFF_MM1;  float* mm2 = base + OFF_MM2;
    float* sbuf = base + OFF_SBUF;

    // Single-sync grab: the read->next-write window always crosses the
    // __syncthreads at the end of gemm_tile's last chunk, so one sync suffices.
#define GRAB_TILE(id_)  { if (tid == 0) s_id = (int)atomicAdd(&g_work, 1u); \
                          __syncthreads(); (id_) = s_id; }

    // zero recurrent state (h1t,c1t,h2t,c2t contiguous)
    for (int i = bid * 256 + tid; i < 4 * BH; i += nct * 256) h1t[i] = 0.0f;
    grid_barrier(nct, bid);

    for (int t = 0; t < Ss; t++) {
        const float* xt = base + OFF_X + (size_t)t * FEATf * Bb;

        // ---- Phase A : 272 tiles ----
        for (;;) {
            int id; GRAB_TILE(id);
            if (id >= 272) break;
            if (id < 16) {
                int hf = id >> 3, j = id & 7;
                gemm_tile(smemf, smemu, xt, base + OFF_WSI, 512, hf*288, 9, j*64, base + OFF_ZBA + (size_t)hf*BMID);
            } else if (id < 48) {
                int i2 = id - 16, q = i2 >> 3, j = i2 & 7;
                gemm_tile(smemf, smemu, h1t, base + OFF_WSH, 512, q*256, 8, j*64, base + OFF_ZBB + (size_t)q*BMID);
            } else if (id < 80) {
                int i2 = id - 48, hf = i2 >> 4, j = i2 & 15;
                gemm_tile(smemf, smemu, xt, base + OFF_WMX1, 1024, hf*288, 9, j*64, base + OFF_M1A + (size_t)hf*BH);
            } else if (id < 144) {
                int i2 = id - 80, q = i2 >> 4, j = i2 & 15;
                gemm_tile(smemf, smemu, h1t, base + OFF_WMH1, 1024, q*256, 8, j*64, base + OFF_M1B + (size_t)q*BH);
            } else {
                int i2 = id - 144, hf = i2 >> 6, j = i2 & 63;
                gemm_tile(smemf, smemu, xt, base + OFF_WIH1, 4096, hf*288, 9, j*64, base + OFF_Z1A + (size_t)hf*B4H);
            }
        }
        grid_barrier(nct, bid);

        // ---- Phase A2 : combine mm1 + boundary ----
        {
            const float* m1a0 = base + OFF_M1A;           const float* m1a1 = m1a0 + BH;
            const float* m1b0 = base + OFF_M1B;           const float* m1b1 = m1b0 + BH;
            const float* m1b2 = m1b0 + 2*BH;              const float* m1b3 = m1b0 + 3*BH;
            for (int idx = bid * 256 + tid; idx < BH; idx += nct * 256) {
                int b = idx >> 10, h = idx & 1023;
                size_t s = (size_t)b * 1024 + h;
                float ma = m1a0[s] + m1a1[s];
                float mb = m1b0[s] + m1b1[s] + m1b2[s] + m1b3[s];
                mm1[h * 128 + b] = ma * mb;
            }
            if (bid < 16) {
                const float* za0 = base + OFF_ZBA; const float* za1 = za0 + BMID;
                const float* zb0 = base + OFF_ZBB; const float* zb1 = zb0 + BMID;
                const float* zb2 = zb0 + 2*BMID;   const float* zb3 = zb0 + 3*BMID;
                int w = tid >> 5, lane = tid & 31;
                int b = bid * 8 + w;
                float sum = 0.0f;
                for (int j = lane; j < MIDm; j += 32) {
                    size_t s = (size_t)b * 512 + j;
                    float z = za0[s] + za1[s] + zb0[s] + zb1[s] + zb2[s] + zb3[s] + b_bd[j];
                    sum += z * vs[j];
                }
#pragma unroll
                for (int o = 16; o > 0; o >>= 1) sum += __shfl_down_sync(0xffffffffu, sum, o);
                if (lane == 0) {
                    float p = 1.0f / (1.0f + expf(-sum));
                    float bin = (p > 0.5f) ? 1.0f : 0.0f;
                    float sv = p + (bin - p);
                    sbuf[b] = sv;
                    if (b == 0) {
                        g_flag = sv;
                        if (OUT_FLAGS + t < out_size) out[OUT_FLAGS + t] = sv;
                    }
                }
            }
        }
        grid_barrier(nct, bid);

        // ---- Phase B : z1b = mm1 @ Whh1^T, 256 tiles (K=256) ----
        for (;;) {
            int id; GRAB_TILE(id);
            if (id >= 256) break;
            int q = id >> 6, j = id & 63;
            gemm_tile(smemf, smemu, mm1, base + OFF_WHH1, 4096, q*256, 8, j*64, base + OFF_Z1B + (size_t)q*B4H);
        }
        grid_barrier(nct, bid);

        // ---- Phase C : gates1 ----
        {
            const float* za0 = base + OFF_Z1A; const float* za1 = za0 + B4H;
            const float* zb0 = base + OFF_Z1B; const float* zb1 = zb0 + B4H;
            const float* zb2 = zb0 + 2*B4H;    const float* zb3 = zb0 + 3*B4H;
            for (int idx = bid * 256 + tid; idx < BH; idx += nct * 256) {
                int b = idx >> 10, h = idx & 1023;
                size_t zi = (size_t)b * 4096 + h;
#define GSUM(g) (za0[zi+(g)*1024]+za1[zi+(g)*1024]+zb0[zi+(g)*1024]+zb1[zi+(g)*1024]+zb2[zi+(g)*1024]+zb3[zi+(g)*1024]+b1[(g)*1024+h])
                float iz = GSUM(0), fz = GSUM(1), gz = GSUM(2), oz = GSUM(3);
#undef GSUM
                int s = h * 128 + b;
                float cn = sigm(fz) * c1t[s] + sigm(iz) * tanhf(gz);
                float hn = sigm(oz) * tanhf(cn);
                float sv = sbuf[b];
                float om = 1.0f - sv;
                x2t[s] = hn * sv;
                h1t[s] = hn * om;
                c1t[s] = cn * om;
            }
        }
        grid_barrier(nct, bid);

        const float fl = *(volatile float*)&g_flag;

        if (fl > 0.5f) {
            // ---- Phase D : 384 tiles (K=256) ----
            for (;;) {
                int id; GRAB_TILE(id);
                if (id >= 384) break;
                if (id < 64) {
                    int q = id >> 4, j = id & 15;
                    gemm_tile(smemf, smemu, x2t, base + OFF_WMX2, 1024, q*256, 8, j*64, base + OFF_M2A + (size_t)q*BH);
                } else if (id < 128) {
                    int i2 = id - 64, q = i2 >> 4, j = i2 & 15;
                    gemm_tile(smemf, smemu, h2t, base + OFF_WMH2, 1024, q*256, 8, j*64, base + OFF_M2B + (size_t)q*BH);
                } else {
                    int i2 = id - 128, q = i2 >> 6, j = i2 & 63;
                    gemm_tile(smemf, smemu, x2t, base + OFF_WIH2, 4096, q*256, 8, j*64, base + OFF_Z2A + (size_t)q*B4H);
                }
            }
            grid_barrier(nct, bid);

            // ---- Phase D2 : combine mm2 ----
            {
                const float* a0 = base + OFF_M2A;
                const float* e0 = base + OFF_M2B;
                for (int idx = bid * 256 + tid; idx < BH; idx += nct * 256) {
                    int b = idx >> 10, h = idx & 1023;
                    size_t s = (size_t)b * 1024 + h;
                    float ma = a0[s] + a0[BH + s] + a0[2*BH + s] + a0[3*BH + s];
                    float mb = e0[s] + e0[BH + s] + e0[2*BH + s] + e0[3*BH + s];
                    mm2[h * 128 + b] = ma * mb;
                }
            }
            grid_barrier(nct, bid);

            // ---- Phase E : z2b, 256 tiles (K=256) ----
            for (;;) {
                int id; GRAB_TILE(id);
                if (id >= 256) break;
                int q = id >> 6, j = id & 63;
                gemm_tile(smemf, smemu, mm2, base + OFF_WHH2, 4096, q*256, 8, j*64, base + OFF_Z2B + (size_t)q*B4H);
            }
            grid_barrier(nct, bid);
        }

        // ---- Phase F : gates2 / copy (no trailing barrier; every buffer F
        // touches is >=1 full barrier away from any t+1 writer/reader) ----
        {
            const float* za = base + OFF_Z2A;
            const float* ze = base + OFF_Z2B;
            for (int idx = bid * 256 + tid; idx < BH; idx += nct * 256) {
                int b = idx >> 10, h = idx & 1023;
                size_t oidx = (size_t)b * Ss * Hh + (size_t)t * Hh + h;
                int s = h * 128 + b;
                if (fl > 0.5f) {
                    size_t zi = (size_t)b * 4096 + h;
#define GSUM(g) (za[zi+(g)*1024] + za[B4H+zi+(g)*1024] + za[2*B4H+zi+(g)*1024] + za[3*B4H+zi+(g)*1024] + \
                 ze[zi+(g)*1024] + ze[B4H+zi+(g)*1024] + ze[2*B4H+zi+(g)*1024] + ze[3*B4H+zi+(g)*1024] + b2[(g)*1024+h])
                    float iz = GSUM(0), fz = GSUM(1), gz = GSUM(2), oz = GSUM(3);
#undef GSUM
                    float cn = sigm(fz) * c2t[s] + sigm(iz) * tanhf(gz);
                    float hn = sigm(oz) * tanhf(cn);
                    h2t[s] = hn;
                    c2t[s] = cn;
                    out[oidx] = hn;
                } else {
                    out[oidx] = h2t[s];
                }
            }
        }
    }

    // ---- tail: final states ----
    grid_barrier(nct, bid);
    for (int idx = bid * 256 + tid; idx < BH; idx += nct * 256) {
        int b = idx >> 10, h = idx & 1023;
        int s = h * 128 + b;
        if (OUT_H2F + idx < out_size) out[OUT_H2F + (size_t)b * 1024 + h] = h2t[s];
        if (OUT_C2F + idx < out_size) out[OUT_C2F + (size_t)b * 1024 + h] = c2t[s];
    }
#undef GRAB_TILE
}

// ---------------------------------------------------------------- weight transpose
// src [N][K] row-major  ->  dst [K][N]
__global__ void transpose_kernel(const float* __restrict__ src, float* __restrict__ dst,
                                 int N, int K)
{
    __shared__ float tile[32][33];
    int kb = blockIdx.x * 32, nb = blockIdx.y * 32;
    int tx = threadIdx.x, ty = threadIdx.y;
#pragma unroll
    for (int r = 0; r < 4; r++)
        tile[ty + r * 8][tx] = src[(size_t)(nb + ty + r * 8) * K + kb + tx];
    __syncthreads();
#pragma unroll
    for (int r = 0; r < 4; r++)
        dst[(size_t)(kb + ty + r * 8) * N + nb + tx] = tile[tx][ty + r * 8];
}

// ---------------------------------------------------------------- embedding gather
// X[t][f][b] (k-major per timestep)
__global__ void gather_kernel(const int* __restrict__ enc, const int* __restrict__ xenc,
                              const float* __restrict__ wemb, const float* __restrict__ xemb,
                              float* __restrict__ X)
{
    int b = blockIdx.x, t = blockIdx.y, tid = threadIdx.x;
    __shared__ int sid, sxid;
    if (tid == 0) { sid = enc[b * Ss + t]; sxid = xenc[b * Ss + t]; }
    __syncthreads();
    int id = sid, xid = sxid;
    float* dst = X + (size_t)t * FEATf * Bb + b;
    for (int f = tid; f < 512; f += 128)
        dst[(size_t)f * 128] = wemb[(size_t)id * 512 + f];
    int f = 512 + tid;
    if (f < 576)
        dst[(size_t)f * 128] = xemb[xid * 64 + (f - 512)];
}

// ----------------------------------------------------------------
extern "C" void kernel_launch(void* const* d_in, const int* in_sizes, int n_in,
                              void* d_out, int out_size)
{
    const int*   enc  = (const int*)d_in[0];
    const int*   xenc = (const int*)d_in[1];
    const float* wemb = (const float*)d_in[2];
    const float* xemb = (const float*)d_in[3];
    const float* Wsi  = (const float*)d_in[4];
    const float* Wsh  = (const float*)d_in[5];
    const float* b_bd = (const float*)d_in[6];
    const float* vs   = (const float*)d_in[7];
    const float* Wmx1 = (const float*)d_in[8];
    const float* Wmh1 = (const float*)d_in[9];
    const float* Wih1 = (const float*)d_in[10];
    const float* Whh1 = (const float*)d_in[11];
    const float* b1   = (const float*)d_in[12];
    const float* Wmx2 = (const float*)d_in[13];
    const float* Wmh2 = (const float*)d_in[14];
    const float* Wih2 = (const float*)d_in[15];
    const float* Whh2 = (const float*)d_in[16];
    const float* b2   = (const float*)d_in[17];
    float* out = (float*)d_out;

    float* base = nullptr;
    cudaGetSymbolAddress((void**)&base, g_scratch);

    gather_kernel<<<dim3(Bb, Ss), 128>>>(enc, xenc, wemb, xemb, base + OFF_X);

    struct TJ { const float* src; size_t dst; int N, K; };
    TJ jobs[10] = {
        { Wsi,  OFF_WSI,  512,  576  },
        { Wsh,  OFF_WSH,  512,  1024 },
        { Wmx1, OFF_WMX1, 1024, 576  },
        { Wmh1, OFF_WMH1, 1024, 1024 },
        { Wih1, OFF_WIH1, 4096, 576  },
        { Whh1, OFF_WHH1, 4096, 1024 },
        { Wmx2, OFF_WMX2, 1024, 1024 },
        { Wmh2, OFF_WMH2, 1024, 1024 },
        { Wih2, OFF_WIH2, 4096, 1024 },
        { Whh2, OFF_WHH2, 4096, 1024 },
    };
    for (int i = 0; i < 10; i++)
        transpose_kernel<<<dim3(jobs[i].K / 32, jobs[i].N / 32), dim3(32, 8)>>>(
            jobs[i].src, base + jobs[i].dst, jobs[i].N, jobs[i].K);

    int nsm = 148;
    cudaDeviceGetAttribute(&nsm, cudaDevAttrMultiProcessorCount, 0);

    const int smem_bytes = (2 * 4096 + 2 * 2048) * 4;  // 49152
    cudaFuncSetAttribute(enc_persistent, cudaFuncAttributeMaxDynamicSharedMemorySize, smem_bytes);

    int occ = 1;
    cudaOccupancyMaxActiveBlocksPerMultiprocessor(&occ, enc_persistent, 256, smem_bytes);
    if (occ < 1) occ = 1;
    if (occ > 2) occ = 2;

    enc_persistent<<<nsm * occ, 256, smem_bytes>>>(b_bd, vs, b1, b2, out, out_size);
}